// round 10
// baseline (speedup 1.0000x reference)
#include <cuda_runtime.h>
#include <cuda_fp16.h>
#include <math.h>
#include <stdint.h>

#define N_TOK  100000
#define C      128
#define CHUNK1 352
#define NB1    ((N_TOK + CHUNK1 - 1) / CHUNK1)   // 285
#define NT     128
#define NTILES ((N_TOK + NT - 1) / NT)            // 782
#define NBLK   148

typedef unsigned long long ull;

// ---------------- scratch ----------------------------------------------------
__device__ float g_part[NB1 * C * C];
__device__ float g_spec[C * C];
__device__ float g_mixed[C * C];                 // mixed [o][k]
__device__ float g_pm[C * NBLK];
__device__ float g_ps[C * NBLK];
__device__ float g_max[C];
__device__ float g_sinv[C];

// ---------------- FFMA2 helpers (GEMM1) --------------------------------------
__device__ __forceinline__ ull pack2(float lo, float hi) {
    ull r; asm("mov.b64 %0, {%1, %2};" : "=l"(r) : "f"(lo), "f"(hi)); return r;
}
__device__ __forceinline__ void unpack2(ull v, float& lo, float& hi) {
    asm("mov.b64 {%0, %1}, %2;" : "=f"(lo), "=f"(hi) : "l"(v));
}
__device__ __forceinline__ void fma2(ull& d, ull a, ull b) {
    asm("fma.rn.f32x2 %0, %1, %2, %0;" : "+l"(d) : "l"(a), "l"(b));
}
__device__ __forceinline__ void comb(float& m, float& s, float m2, float s2) {
    float M = fmaxf(m, m2);
    float S = 0.f;
    if (m  > -INFINITY) S += s  * __expf(m  - M);
    if (m2 > -INFINITY) S += s2 * __expf(m2 - M);
    m = M; s = S;
}

// ---------------- fp16 warp-MMA helpers --------------------------------------
__device__ __forceinline__ uint32_t smem_u32(const void* p) {
    uint32_t a;
    asm("{ .reg .u64 t; cvta.to.shared.u64 t, %1; cvt.u32.u64 %0, t; }"
        : "=r"(a) : "l"(p));
    return a;
}
__device__ __forceinline__ void ldsm4(uint32_t& r0, uint32_t& r1,
                                      uint32_t& r2, uint32_t& r3, uint32_t addr) {
    asm volatile("ldmatrix.sync.aligned.m8n8.x4.shared.b16 {%0,%1,%2,%3}, [%4];"
                 : "=r"(r0), "=r"(r1), "=r"(r2), "=r"(r3) : "r"(addr));
}
__device__ __forceinline__ void mma_f16(float* d, const uint32_t* a,
                                        const uint32_t* b) {
    asm volatile(
        "mma.sync.aligned.m16n8k16.row.col.f32.f16.f16.f32 "
        "{%0,%1,%2,%3}, {%4,%5,%6,%7}, {%8,%9}, {%0,%1,%2,%3};"
        : "+f"(d[0]), "+f"(d[1]), "+f"(d[2]), "+f"(d[3])
        : "r"(a[0]), "r"(a[1]), "r"(a[2]), "r"(a[3]), "r"(b[0]), "r"(b[1]));
}
__device__ __forceinline__ uint32_t h2_bits(__half2 h) {
    union { __half2 h; uint32_t u; } c; c.h = h; return c.u;
}
// split fp32x4 -> fp16 hi + fp16 lo via packed half2 conversions
__device__ __forceinline__ void split4(float4 v, uint2& H, uint2& L) {
    __half2 h01 = __float22half2_rn(make_float2(v.x, v.y));
    __half2 h23 = __float22half2_rn(make_float2(v.z, v.w));
    float2 b01 = __half22float2(h01);
    float2 b23 = __half22float2(h23);
    __half2 l01 = __float22half2_rn(make_float2(v.x - b01.x, v.y - b01.y));
    __half2 l23 = __float22half2_rn(make_float2(v.z - b23.x, v.w - b23.y));
    H.x = h2_bits(h01); H.y = h2_bits(h23);
    L.x = h2_bits(l01); L.y = h2_bits(l23);
}

// ---------------- 1) GEMM1 partials (FFMA2) ----------------------------------
__global__ void __launch_bounds__(256, 2) k_gemm1(const float* __restrict__ U,
                                                  const float* __restrict__ x) {
    __shared__ float u_s[32][C];
    __shared__ float x_s[32][C];
    int b  = blockIdx.x;
    int n0 = b * CHUNK1;
    int n1 = min(n0 + CHUNK1, N_TOK);
    int tid = threadIdx.x;
    int tx = tid & 15, ty = tid >> 4;

    ull acc[8][4];
    ull z = pack2(0.0f, 0.0f);
#pragma unroll
    for (int i = 0; i < 8; i++)
#pragma unroll
        for (int j = 0; j < 4; j++) acc[i][j] = z;

    for (int nb = n0; nb < n1; nb += 32) {
#pragma unroll
        for (int t4 = 0; t4 < 4; t4++) {
            int f  = t4 * 256 + tid;
            int r  = f >> 5, c4 = f & 31;
            int n  = nb + r;
            float4 vu, vx;
            if (n < n1) {
                vu = ((const float4*)(U + (size_t)n * C))[c4];
                vx = ((const float4*)(x + (size_t)n * C))[c4];
            } else {
                vu = make_float4(0.f, 0.f, 0.f, 0.f);
                vx = vu;
            }
            ((float4*)&u_s[r][0])[c4] = vu;
            ((float4*)&x_s[r][0])[c4] = vx;
        }
        __syncthreads();
#pragma unroll 2
        for (int r = 0; r < 32; ++r) {
            float au[8];
            *(float4*)&au[0] = *(const float4*)&u_s[r][8 * ty];
            *(float4*)&au[4] = *(const float4*)&u_s[r][8 * ty + 4];
            ulonglong2 bl0 = *(const ulonglong2*)&x_s[r][4 * tx];
            ulonglong2 bl1 = *(const ulonglong2*)&x_s[r][4 * tx + 64];
            ull bb[4] = { bl0.x, bl0.y, bl1.x, bl1.y };
#pragma unroll
            for (int ii = 0; ii < 8; ii++) {
                ull a2 = pack2(au[ii], au[ii]);
#pragma unroll
                for (int j = 0; j < 4; j++) fma2(acc[ii][j], a2, bb[j]);
            }
        }
        __syncthreads();
    }

    float* dst = g_part + (size_t)b * (C * C);
#pragma unroll
    for (int ii = 0; ii < 8; ii++) {
        float v[8];
#pragma unroll
        for (int j = 0; j < 4; j++) unpack2(acc[ii][j], v[2 * j], v[2 * j + 1]);
        float* row = dst + (8 * ty + ii) * C;
        *(float4*)&row[4 * tx]      = make_float4(v[0], v[1], v[2], v[3]);
        *(float4*)&row[4 * tx + 64] = make_float4(v[4], v[5], v[6], v[7]);
    }
}

// ---------------- 2) reduce partials -> g_spec -------------------------------
__global__ void k_rsum() {
    int j = blockIdx.x * 256 + threadIdx.x;
    float s0 = 0.f, s1 = 0.f, s2 = 0.f, s3 = 0.f;
    int b = 0;
    for (; b + 4 <= NB1; b += 4) {
        s0 += g_part[(b + 0) * (C * C) + j];
        s1 += g_part[(b + 1) * (C * C) + j];
        s2 += g_part[(b + 2) * (C * C) + j];
        s3 += g_part[(b + 3) * (C * C) + j];
    }
    for (; b < NB1; b++) s0 += g_part[b * (C * C) + j];
    g_spec[j] = (s0 + s1) + (s2 + s3);
}

// ---------------- 3) mixed -> g_mixed[o][k] ----------------------------------
__global__ void __launch_bounds__(256) k_mixed_w(const float* __restrict__ coeffs) {
    int gw   = blockIdx.x * 8 + (threadIdx.x >> 5);
    int lane = threadIdx.x & 31;
    int o = gw >> 5, k0 = (gw & 31) * 4;
    float s[4];
#pragma unroll
    for (int kk = 0; kk < 4; kk++) {
        int k = k0 + kk;
        float4 a  = ((const float4*)(coeffs + (((size_t)o * C + k) << 7)))[lane];
        float4 bv = ((const float4*)(g_spec + (k << 7)))[lane];
        s[kk] = a.x * bv.x + a.y * bv.y + a.z * bv.z + a.w * bv.w;
    }
#pragma unroll
    for (int off = 16; off; off >>= 1)
#pragma unroll
        for (int kk = 0; kk < 4; kk++)
            s[kk] += __shfl_xor_sync(0xffffffffu, s[kk], off);
    if (lane == 0) {
#pragma unroll
        for (int kk = 0; kk < 4; kk++) g_mixed[(size_t)o * C + k0 + kk] = s[kk];
    }
}

// ---------------- 4) GEMM2: persistent fp16-split-3 MMA, cp.async pipelined --
#define ROWH 136                 // halves per smem row (272B)
#define ROWB 272
#define A_HI 0
#define A_LO 34816
#define B_HI 69632
#define B_LO 104448
#define RAWB 139264              // raw fp32 U tile staging (64KB)
#define SM_TOT 204800
#define SSTG 132                 // staging stride (floats)
#define SUM_THR (-15.0f)

__global__ void __launch_bounds__(512, 1) k_gemm3_p(const float* __restrict__ U,
                                                    float* __restrict__ out) {
    extern __shared__ char smem[];
    uint32_t sb = smem_u32(smem);
    __shared__ float red_m[4][C], red_s[4][C];
    int tid = threadIdx.x, wid = tid >> 5, lid = tid & 31;
    int bid = blockIdx.x;
    int ob  = (wid & 3) * 32;           // warp o-base
    int nbw = (wid >> 2) * 32;          // warp n-base

    int arow_l = (lid & 7) + ((lid >> 3) & 1) * 8;
    int acol_l = ((lid >> 4) & 1) * 8;
    int brow_l = (lid & 7) + ((lid >> 4) & 1) * 8;
    int bcol_l = ((lid >> 3) & 1) * 8;

    // --- issue cp.async prefetch for a tile into RAW ---
    auto cp_tile = [&](int t) {
        int n0 = t * NT;
        int nvalid = min(NT, N_TOK - n0);
#pragma unroll
        for (int i = 0; i < 8; i++) {
            int f = i * 512 + tid;
            int r = f >> 5, c4 = f & 31;
            int ok = (r < nvalid);
            const float* g = U + (size_t)(n0 + (ok ? r : 0)) * C + 4 * c4;
            uint32_t dst = sb + RAWB + f * 16;
            int sz = ok ? 16 : 0;
            asm volatile("cp.async.cg.shared.global [%0], [%1], 16, %2;"
                         :: "r"(dst), "l"(g), "r"(sz) : "memory");
        }
        asm volatile("cp.async.commit_group;" ::: "memory");
    };

    // ---- prefetch first tile, then A fill (overlaps) ----
    if (bid < NTILES) cp_tile(bid);
#pragma unroll
    for (int i = 0; i < 8; i++) {
        int f = i * 512 + tid;
        int r = f >> 5, c4 = f & 31;
        float4 v = ((const float4*)(g_mixed + (size_t)r * C))[c4];
        uint2 H, L;
        split4(v, H, L);
        *(uint2*)(smem + A_HI + r * ROWB + 8 * c4) = H;
        *(uint2*)(smem + A_LO + r * ROWB + 8 * c4) = L;
    }

    float pm[4] = { -INFINITY, -INFINITY, -INFINITY, -INFINITY };
    float ps[4] = { 0.f, 0.f, 0.f, 0.f };

    for (int t = bid; t < NTILES; t += NBLK) {
        int n0 = t * NT;
        int nvalid = min(NT, N_TOK - n0);

        // ---- wait prefetch; convert RAW -> B hi/lo ----
        asm volatile("cp.async.wait_group 0;" ::: "memory");
        __syncthreads();               // also fences prev-tile stg reads
#pragma unroll
        for (int i = 0; i < 8; i++) {
            int f = i * 512 + tid;
            int r = f >> 5, c4 = f & 31;
            float4 v = *(const float4*)(smem + RAWB + f * 16);
            uint2 H, L;
            split4(v, H, L);
            *(uint2*)(smem + B_HI + r * ROWB + 8 * c4) = H;
            *(uint2*)(smem + B_LO + r * ROWB + 8 * c4) = L;
        }
        __syncthreads();

        // ---- prefetch next tile (overlaps MMA + epilogue) ----
        if (t + NBLK < NTILES) cp_tile(t + NBLK);

        float d[2][4][4];
#pragma unroll
        for (int mf = 0; mf < 2; mf++)
#pragma unroll
            for (int nf = 0; nf < 4; nf++)
#pragma unroll
                for (int q = 0; q < 4; q++) d[mf][nf][q] = 0.f;

#pragma unroll
        for (int pass = 0; pass < 3; pass++) {
            uint32_t aB = sb + ((pass == 2) ? A_LO : A_HI);
            uint32_t bB = sb + ((pass == 1) ? B_LO : B_HI);
#pragma unroll
            for (int ks = 0; ks < 8; ks++) {
                int k0 = 16 * ks;
                uint32_t a[2][4], bq[2][4];
#pragma unroll
                for (int mf = 0; mf < 2; mf++) {
                    uint32_t addr = aB +
                        ((ob + mf * 16 + arow_l) * ROWH + k0 + acol_l) * 2;
                    ldsm4(a[mf][0], a[mf][1], a[mf][2], a[mf][3], addr);
                }
#pragma unroll
                for (int p4 = 0; p4 < 2; p4++) {
                    uint32_t addr = bB +
                        ((nbw + p4 * 16 + brow_l) * ROWH + k0 + bcol_l) * 2;
                    ldsm4(bq[p4][0], bq[p4][1], bq[p4][2], bq[p4][3], addr);
                }
#pragma unroll
                for (int mf = 0; mf < 2; mf++)
#pragma unroll
                    for (int nf = 0; nf < 4; nf++)
                        mma_f16(d[mf][nf], a[mf], &bq[nf >> 1][2 * (nf & 1)]);
            }
        }
        __syncthreads();               // all MMA done before staging reuses B

        // ---- softmax partials: tile-local max, thresholded exp sum ----
        // (padded logits are 0; true column max ~+1.8e5 => fakes vanish)
#pragma unroll
        for (int mf = 0; mf < 2; mf++)
#pragma unroll
            for (int h = 0; h < 2; h++) {
                int q = 2 * mf + h;
                float mt = -INFINITY;
#pragma unroll
                for (int nf = 0; nf < 4; nf++)
                    mt = fmaxf(mt, fmaxf(d[mf][nf][2 * h], d[mf][nf][2 * h + 1]));
                if (mt > pm[q]) {
                    ps[q] *= __expf(pm[q] - mt);
                    pm[q] = mt;
                }
                float m = pm[q];
#pragma unroll
                for (int nf = 0; nf < 4; nf++) {
                    float t0 = d[mf][nf][2 * h] - m;
                    float t1 = d[mf][nf][2 * h + 1] - m;
                    if (t0 > SUM_THR) ps[q] += __expf(t0);
                    if (t1 > SUM_THR) ps[q] += __expf(t1);
                }
            }

        // ---- stage logits [n][o] into retired B region ----
        float* stg = (float*)(smem + B_HI);
#pragma unroll
        for (int mf = 0; mf < 2; mf++)
#pragma unroll
            for (int nf = 0; nf < 4; nf++) {
                int n = nbw + nf * 8 + 2 * (lid & 3);
                int o = ob + mf * 16 + (lid >> 2);
                stg[n * SSTG + o]           = d[mf][nf][0];
                stg[(n + 1) * SSTG + o]     = d[mf][nf][1];
                stg[n * SSTG + o + 8]       = d[mf][nf][2];
                stg[(n + 1) * SSTG + o + 8] = d[mf][nf][3];
            }
        __syncthreads();

        // ---- coalesced logit store out[n][o] ----
#pragma unroll
        for (int i = 0; i < 8; i++) {
            int f = i * 512 + tid;
            int r = f >> 5, c4 = f & 31;
            if (r < nvalid) {
                float4 v = *(const float4*)&stg[r * SSTG + 4 * c4];
                ((float4*)(out + (size_t)(n0 + r) * C))[c4] = v;
            }
        }
    }

    // ---- per-block softmax partials ----
#pragma unroll
    for (int off = 1; off <= 2; off <<= 1) {
#pragma unroll
        for (int q = 0; q < 4; q++) {
            float m2 = __shfl_xor_sync(0xffffffffu, pm[q], off);
            float s2 = __shfl_xor_sync(0xffffffffu, ps[q], off);
            comb(pm[q], ps[q], m2, s2);
        }
    }
    if ((lid & 3) == 0) {
#pragma unroll
        for (int q = 0; q < 4; q++) {
            int o = ob + (q >> 1) * 16 + (q & 1) * 8 + (lid >> 2);
            red_m[wid >> 2][o] = pm[q];
            red_s[wid >> 2][o] = ps[q];
        }
    }
    __syncthreads();
    if (tid < C) {
        float M = red_m[0][tid], S = red_s[0][tid];
        comb(M, S, red_m[1][tid], red_s[1][tid]);
        comb(M, S, red_m[2][tid], red_s[2][tid]);
        comb(M, S, red_m[3][tid], red_s[3][tid]);
        g_pm[(size_t)tid * NBLK + bid] = M;
        g_ps[(size_t)tid * NBLK + bid] = S;
    }
}

// ---------------- 5) combine softmax partials --------------------------------
__global__ void k_softmax_par() {
    int o = blockIdx.x;
    float M = -INFINITY, S = 0.f;
    for (int b = threadIdx.x; b < NBLK; b += 256)
        comb(M, S, g_pm[(size_t)o * NBLK + b], g_ps[(size_t)o * NBLK + b]);
#pragma unroll
    for (int off = 16; off; off >>= 1) {
        float m2 = __shfl_xor_sync(0xffffffffu, M, off);
        float s2 = __shfl_xor_sync(0xffffffffu, S, off);
        comb(M, S, m2, s2);
    }
    __shared__ float sm[8], ss[8];
    int wq = threadIdx.x >> 5, lane = threadIdx.x & 31;
    if (lane == 0) { sm[wq] = M; ss[wq] = S; }
    __syncthreads();
    if (threadIdx.x == 0) {
#pragma unroll
        for (int i = 1; i < 8; i++) comb(sm[0], ss[0], sm[i], ss[i]);
        g_max[o]  = sm[0];
        g_sinv[o] = 1.0f / ss[0];
    }
}

// ---------------- 6) final: thresholded exp + normalize ----------------------
__global__ void k_final2(float* __restrict__ out) {
    int base = blockIdx.x * 512 + threadIdx.x;
#pragma unroll
    for (int h = 0; h < 2; h++) {
        int f = base + h * 256;
        float4 v = ((const float4*)out)[f];
        int og = f & 31;
        float4 M = ((const float4*)g_max)[og];
        float4 I = ((const float4*)g_sinv)[og];
        float t0 = v.x - M.x, t1 = v.y - M.y, t2 = v.z - M.z, t3 = v.w - M.w;
        v.x = (t0 > -87.f) ? __expf(t0) * I.x : 0.f;
        v.y = (t1 > -87.f) ? __expf(t1) * I.y : 0.f;
        v.z = (t2 > -87.f) ? __expf(t2) * I.z : 0.f;
        v.w = (t3 > -87.f) ? __expf(t3) * I.w : 0.f;
        ((float4*)out)[f] = v;
    }
}

// ---------------- launcher ---------------------------------------------------
extern "C" void kernel_launch(void* const* d_in, const int* in_sizes, int n_in,
                              void* d_out, int out_size) {
    const float* x      = (const float*)d_in[0];
    const float* U      = (const float*)d_in[1];
    const float* coeffs = (const float*)d_in[2];
    float* out = (float*)d_out;

    cudaFuncSetAttribute(k_gemm3_p, cudaFuncAttributeMaxDynamicSharedMemorySize,
                         SM_TOT);

    k_gemm1<<<NB1, 256>>>(U, x);
    k_rsum<<<64, 256>>>();
    k_mixed_w<<<512, 256>>>(coeffs);
    k_gemm3_p<<<NBLK, 512, SM_TOT>>>(U, out);
    k_softmax_par<<<C, 256>>>();
    k_final2<<<N_TOK * C / 4 / 512, 256>>>(out);
}

// round 11
// speedup vs baseline: 1.3160x; 1.3160x over previous
#include <cuda_runtime.h>
#include <cuda_fp16.h>
#include <math.h>
#include <stdint.h>

#define N_TOK  100000
#define C      128
#define NT     128
#define NTILES ((N_TOK + NT - 1) / NT)            // 782  (GEMM2 tiles)
#define NBLK   148
#define CH     64
#define NCH    ((N_TOK + CH - 1) / CH)            // 1563 (GEMM1 chunks)

typedef unsigned long long ull;

// ---------------- scratch ----------------------------------------------------
__device__ float g_part[NBLK * C * C];
__device__ float g_spec[C * C];
__device__ float g_mixed[C * C];                 // mixed [o][k]
__device__ float g_pm[C * NBLK];
__device__ float g_ps[C * NBLK];
__device__ float g_max[C];
__device__ float g_sinv[C];

__device__ __forceinline__ void comb(float& m, float& s, float m2, float s2) {
    float M = fmaxf(m, m2);
    float S = 0.f;
    if (m  > -INFINITY) S += s  * __expf(m  - M);
    if (m2 > -INFINITY) S += s2 * __expf(m2 - M);
    m = M; s = S;
}

// ---------------- fp16 warp-MMA helpers --------------------------------------
__device__ __forceinline__ uint32_t smem_u32(const void* p) {
    uint32_t a;
    asm("{ .reg .u64 t; cvta.to.shared.u64 t, %1; cvt.u32.u64 %0, t; }"
        : "=r"(a) : "l"(p));
    return a;
}
__device__ __forceinline__ void ldsm4(uint32_t& r0, uint32_t& r1,
                                      uint32_t& r2, uint32_t& r3, uint32_t addr) {
    asm volatile("ldmatrix.sync.aligned.m8n8.x4.shared.b16 {%0,%1,%2,%3}, [%4];"
                 : "=r"(r0), "=r"(r1), "=r"(r2), "=r"(r3) : "r"(addr));
}
__device__ __forceinline__ void ldsm4t(uint32_t& r0, uint32_t& r1,
                                       uint32_t& r2, uint32_t& r3, uint32_t addr) {
    asm volatile("ldmatrix.sync.aligned.m8n8.x4.trans.shared.b16 {%0,%1,%2,%3}, [%4];"
                 : "=r"(r0), "=r"(r1), "=r"(r2), "=r"(r3) : "r"(addr));
}
__device__ __forceinline__ void mma_f16(float* d, const uint32_t* a,
                                        const uint32_t* b) {
    asm volatile(
        "mma.sync.aligned.m16n8k16.row.col.f32.f16.f16.f32 "
        "{%0,%1,%2,%3}, {%4,%5,%6,%7}, {%8,%9}, {%0,%1,%2,%3};"
        : "+f"(d[0]), "+f"(d[1]), "+f"(d[2]), "+f"(d[3])
        : "r"(a[0]), "r"(a[1]), "r"(a[2]), "r"(a[3]), "r"(b[0]), "r"(b[1]));
}
__device__ __forceinline__ uint32_t h2_bits(__half2 h) {
    union { __half2 h; uint32_t u; } c; c.h = h; return c.u;
}
__device__ __forceinline__ void split4(float4 v, uint2& H, uint2& L) {
    __half2 h01 = __float22half2_rn(make_float2(v.x, v.y));
    __half2 h23 = __float22half2_rn(make_float2(v.z, v.w));
    float2 b01 = __half22float2(h01);
    float2 b23 = __half22float2(h23);
    __half2 l01 = __float22half2_rn(make_float2(v.x - b01.x, v.y - b01.y));
    __half2 l23 = __float22half2_rn(make_float2(v.z - b23.x, v.w - b23.y));
    H.x = h2_bits(h01); H.y = h2_bits(h23);
    L.x = h2_bits(l01); L.y = h2_bits(l23);
}
#define ROWH 136
#define ROWB 272

// ---------------- 1) GEMM1: persistent fp16-split-3 MMA ----------------------
// spec[k=128][i=128] = sum_n U[n][k]*x[n][i]; MMA-K = n (trans ldmatrix loads)
#define G1_UH  0
#define G1_UL  17408
#define G1_XH  34816
#define G1_XL  52224
#define G1_RAW 69632
#define G1_SM  200704

__global__ void __launch_bounds__(512, 1) k_gemm1_mma(const float* __restrict__ U,
                                                      const float* __restrict__ x) {
    extern __shared__ char smem[];
    uint32_t sb = smem_u32(smem);
    int tid = threadIdx.x, wid = tid >> 5, lid = tid & 31;
    int bid = blockIdx.x;
    int kb = (wid & 3) * 32;             // spec-k rows (MMA m)
    int ib = (wid >> 2) * 32;            // i cols (MMA n)

    // trans ldmatrix lane maps (mirror of validated normal-mode maps)
    int arow = (lid & 7) + ((lid >> 4) & 1) * 8;   // token offset (K)
    int acol = ((lid >> 3) & 1) * 8;               // m offset
    int brow = (lid & 7) + ((lid >> 3) & 1) * 8;   // token offset (K)
    int bcol = ((lid >> 4) & 1) * 8;               // n offset

    auto cp_chunk = [&](int ch, int buf) {
        int n0 = ch * CH;
        int nv = min(CH, N_TOK - n0);
#pragma unroll
        for (int i = 0; i < 4; i++) {
            int f = i * 512 + tid;
            int r = f >> 5, c4 = f & 31;
            int ok = (r < nv);
            const float* gu = U + (size_t)(n0 + (ok ? r : 0)) * C + 4 * c4;
            const float* gx = x + (size_t)(n0 + (ok ? r : 0)) * C + 4 * c4;
            uint32_t du = sb + G1_RAW + buf * 65536 + f * 16;
            int sz = ok ? 16 : 0;
            asm volatile("cp.async.cg.shared.global [%0], [%1], 16, %2;"
                         :: "r"(du), "l"(gu), "r"(sz) : "memory");
            asm volatile("cp.async.cg.shared.global [%0], [%1], 16, %2;"
                         :: "r"(du + 32768u), "l"(gx), "r"(sz) : "memory");
        }
        asm volatile("cp.async.commit_group;" ::: "memory");
    };

    float d[2][4][4];
#pragma unroll
    for (int mf = 0; mf < 2; mf++)
#pragma unroll
        for (int nf = 0; nf < 4; nf++)
#pragma unroll
            for (int q = 0; q < 4; q++) d[mf][nf][q] = 0.f;

    cp_chunk(bid, 0);
    int it = 0;
    for (int ch = bid; ch < NCH; ch += NBLK, it++) {
        int buf = it & 1;
        if (ch + NBLK < NCH) {
            cp_chunk(ch + NBLK, buf ^ 1);
            asm volatile("cp.async.wait_group 1;" ::: "memory");
        } else {
            asm volatile("cp.async.wait_group 0;" ::: "memory");
        }
        __syncthreads();                 // prev MMA done; raw[buf] ready

        // convert raw -> UH/UL/XH/XL ([token][chan] halves)
#pragma unroll
        for (int i = 0; i < 4; i++) {
            int f = i * 512 + tid;
            int r = f >> 5, c4 = f & 31;
            float4 vu = *(const float4*)(smem + G1_RAW + buf * 65536 + f * 16);
            float4 vx = *(const float4*)(smem + G1_RAW + buf * 65536 + 32768 + f * 16);
            uint2 H, L;
            split4(vu, H, L);
            *(uint2*)(smem + G1_UH + r * ROWB + 8 * c4) = H;
            *(uint2*)(smem + G1_UL + r * ROWB + 8 * c4) = L;
            split4(vx, H, L);
            *(uint2*)(smem + G1_XH + r * ROWB + 8 * c4) = H;
            *(uint2*)(smem + G1_XL + r * ROWB + 8 * c4) = L;
        }
        __syncthreads();

        // 3 passes: Uh*Xh, Uh*Xl, Ul*Xh ; MMA-K = 64 tokens = 4 ksteps
#pragma unroll
        for (int pass = 0; pass < 3; pass++) {
            uint32_t aB = sb + ((pass == 2) ? G1_UL : G1_UH);
            uint32_t bB = sb + ((pass == 1) ? G1_XL : G1_XH);
#pragma unroll
            for (int ks = 0; ks < 4; ks++) {
                int t0 = 16 * ks;
                uint32_t a[2][4], bq[2][4];
#pragma unroll
                for (int mf = 0; mf < 2; mf++) {
                    uint32_t addr = aB +
                        ((t0 + arow) * ROWH + kb + mf * 16 + acol) * 2;
                    ldsm4t(a[mf][0], a[mf][1], a[mf][2], a[mf][3], addr);
                }
#pragma unroll
                for (int p4 = 0; p4 < 2; p4++) {
                    uint32_t addr = bB +
                        ((t0 + brow) * ROWH + ib + p4 * 16 + bcol) * 2;
                    ldsm4t(bq[p4][0], bq[p4][1], bq[p4][2], bq[p4][3], addr);
                }
#pragma unroll
                for (int mf = 0; mf < 2; mf++)
#pragma unroll
                    for (int nf = 0; nf < 4; nf++)
                        mma_f16(d[mf][nf], a[mf], &bq[nf >> 1][2 * (nf & 1)]);
            }
        }
    }

    // store partial: g_part[bid][k][i]
    float* dst = g_part + (size_t)bid * (C * C);
#pragma unroll
    for (int mf = 0; mf < 2; mf++)
#pragma unroll
        for (int nf = 0; nf < 4; nf++) {
            int row = kb + mf * 16 + (lid >> 2);
            int col = ib + nf * 8 + 2 * (lid & 3);
            *(float2*)&dst[row * C + col] =
                make_float2(d[mf][nf][0], d[mf][nf][1]);
            *(float2*)&dst[(row + 8) * C + col] =
                make_float2(d[mf][nf][2], d[mf][nf][3]);
        }
}

// ---------------- 2) reduce partials -> g_spec -------------------------------
__global__ void k_rsum() {
    int j = blockIdx.x * 256 + threadIdx.x;
    float s0 = 0.f, s1 = 0.f, s2 = 0.f, s3 = 0.f;
#pragma unroll 1
    for (int b = 0; b < NBLK; b += 4) {
        s0 += g_part[(b + 0) * (C * C) + j];
        s1 += g_part[(b + 1) * (C * C) + j];
        s2 += g_part[(b + 2) * (C * C) + j];
        s3 += g_part[(b + 3) * (C * C) + j];
    }
    g_spec[j] = (s0 + s1) + (s2 + s3);
}

// ---------------- 3) mixed -> g_mixed[o][k] ----------------------------------
__global__ void __launch_bounds__(256) k_mixed_w(const float* __restrict__ coeffs) {
    int gw   = blockIdx.x * 8 + (threadIdx.x >> 5);
    int lane = threadIdx.x & 31;
    int o = gw >> 5, k0 = (gw & 31) * 4;
    float s[4];
#pragma unroll
    for (int kk = 0; kk < 4; kk++) {
        int k = k0 + kk;
        float4 a  = ((const float4*)(coeffs + (((size_t)o * C + k) << 7)))[lane];
        float4 bv = ((const float4*)(g_spec + (k << 7)))[lane];
        s[kk] = a.x * bv.x + a.y * bv.y + a.z * bv.z + a.w * bv.w;
    }
#pragma unroll
    for (int off = 16; off; off >>= 1)
#pragma unroll
        for (int kk = 0; kk < 4; kk++)
            s[kk] += __shfl_xor_sync(0xffffffffu, s[kk], off);
    if (lane == 0) {
#pragma unroll
        for (int kk = 0; kk < 4; kk++) g_mixed[(size_t)o * C + k0 + kk] = s[kk];
    }
}

// ---------------- 4) GEMM2: persistent fp16-split-3 MMA, cp.async pipelined --
#define A_HI 0
#define A_LO 34816
#define B_HI 69632
#define B_LO 104448
#define RAWB 139264
#define SM_TOT 204800
#define SSTG 132
#define SUM_THR (-15.0f)

__global__ void __launch_bounds__(512, 1) k_gemm3_p(const float* __restrict__ U,
                                                    float* __restrict__ out) {
    extern __shared__ char smem[];
    uint32_t sb = smem_u32(smem);
    __shared__ float red_m[4][C], red_s[4][C];
    int tid = threadIdx.x, wid = tid >> 5, lid = tid & 31;
    int bid = blockIdx.x;
    int ob  = (wid & 3) * 32;
    int nbw = (wid >> 2) * 32;

    int arow_l = (lid & 7) + ((lid >> 3) & 1) * 8;
    int acol_l = ((lid >> 4) & 1) * 8;
    int brow_l = (lid & 7) + ((lid >> 4) & 1) * 8;
    int bcol_l = ((lid >> 3) & 1) * 8;

    auto cp_tile = [&](int t) {
        int n0 = t * NT;
        int nvalid = min(NT, N_TOK - n0);
#pragma unroll
        for (int i = 0; i < 8; i++) {
            int f = i * 512 + tid;
            int r = f >> 5, c4 = f & 31;
            int ok = (r < nvalid);
            const float* g = U + (size_t)(n0 + (ok ? r : 0)) * C + 4 * c4;
            uint32_t dst = sb + RAWB + f * 16;
            int sz = ok ? 16 : 0;
            asm volatile("cp.async.cg.shared.global [%0], [%1], 16, %2;"
                         :: "r"(dst), "l"(g), "r"(sz) : "memory");
        }
        asm volatile("cp.async.commit_group;" ::: "memory");
    };

    if (bid < NTILES) cp_tile(bid);
#pragma unroll
    for (int i = 0; i < 8; i++) {
        int f = i * 512 + tid;
        int r = f >> 5, c4 = f & 31;
        float4 v = ((const float4*)(g_mixed + (size_t)r * C))[c4];
        uint2 H, L;
        split4(v, H, L);
        *(uint2*)(smem + A_HI + r * ROWB + 8 * c4) = H;
        *(uint2*)(smem + A_LO + r * ROWB + 8 * c4) = L;
    }

    float pm[4] = { -INFINITY, -INFINITY, -INFINITY, -INFINITY };
    float ps[4] = { 0.f, 0.f, 0.f, 0.f };

    for (int t = bid; t < NTILES; t += NBLK) {
        int n0 = t * NT;
        int nvalid = min(NT, N_TOK - n0);

        asm volatile("cp.async.wait_group 0;" ::: "memory");
        __syncthreads();
#pragma unroll
        for (int i = 0; i < 8; i++) {
            int f = i * 512 + tid;
            int r = f >> 5, c4 = f & 31;
            float4 v = *(const float4*)(smem + RAWB + f * 16);
            uint2 H, L;
            split4(v, H, L);
            *(uint2*)(smem + B_HI + r * ROWB + 8 * c4) = H;
            *(uint2*)(smem + B_LO + r * ROWB + 8 * c4) = L;
        }
        __syncthreads();

        if (t + NBLK < NTILES) cp_tile(t + NBLK);

        float d[2][4][4];
#pragma unroll
        for (int mf = 0; mf < 2; mf++)
#pragma unroll
            for (int nf = 0; nf < 4; nf++)
#pragma unroll
                for (int q = 0; q < 4; q++) d[mf][nf][q] = 0.f;

#pragma unroll
        for (int pass = 0; pass < 3; pass++) {
            uint32_t aB = sb + ((pass == 2) ? A_LO : A_HI);
            uint32_t bB = sb + ((pass == 1) ? B_LO : B_HI);
#pragma unroll
            for (int ks = 0; ks < 8; ks++) {
                int k0 = 16 * ks;
                uint32_t a[2][4], bq[2][4];
#pragma unroll
                for (int mf = 0; mf < 2; mf++) {
                    uint32_t addr = aB +
                        ((ob + mf * 16 + arow_l) * ROWH + k0 + acol_l) * 2;
                    ldsm4(a[mf][0], a[mf][1], a[mf][2], a[mf][3], addr);
                }
#pragma unroll
                for (int p4 = 0; p4 < 2; p4++) {
                    uint32_t addr = bB +
                        ((nbw + p4 * 16 + brow_l) * ROWH + k0 + bcol_l) * 2;
                    ldsm4(bq[p4][0], bq[p4][1], bq[p4][2], bq[p4][3], addr);
                }
#pragma unroll
                for (int mf = 0; mf < 2; mf++)
#pragma unroll
                    for (int nf = 0; nf < 4; nf++)
                        mma_f16(d[mf][nf], a[mf], &bq[nf >> 1][2 * (nf & 1)]);
            }
        }
        __syncthreads();

#pragma unroll
        for (int mf = 0; mf < 2; mf++)
#pragma unroll
            for (int h = 0; h < 2; h++) {
                int q = 2 * mf + h;
                float mt = -INFINITY;
#pragma unroll
                for (int nf = 0; nf < 4; nf++)
                    mt = fmaxf(mt, fmaxf(d[mf][nf][2 * h], d[mf][nf][2 * h + 1]));
                if (mt > pm[q]) {
                    ps[q] *= __expf(pm[q] - mt);
                    pm[q] = mt;
                }
                float m = pm[q];
#pragma unroll
                for (int nf = 0; nf < 4; nf++) {
                    float t0 = d[mf][nf][2 * h] - m;
                    float t1 = d[mf][nf][2 * h + 1] - m;
                    if (t0 > SUM_THR) ps[q] += __expf(t0);
                    if (t1 > SUM_THR) ps[q] += __expf(t1);
                }
            }

        float* stg = (float*)(smem + B_HI);
#pragma unroll
        for (int mf = 0; mf < 2; mf++)
#pragma unroll
            for (int nf = 0; nf < 4; nf++) {
                int n = nbw + nf * 8 + 2 * (lid & 3);
                int o = ob + mf * 16 + (lid >> 2);
                stg[n * SSTG + o]           = d[mf][nf][0];
                stg[(n + 1) * SSTG + o]     = d[mf][nf][1];
                stg[n * SSTG + o + 8]       = d[mf][nf][2];
                stg[(n + 1) * SSTG + o + 8] = d[mf][nf][3];
            }
        __syncthreads();

#pragma unroll
        for (int i = 0; i < 8; i++) {
            int f = i * 512 + tid;
            int r = f >> 5, c4 = f & 31;
            if (r < nvalid) {
                float4 v = *(const float4*)&stg[r * SSTG + 4 * c4];
                ((float4*)(out + (size_t)(n0 + r) * C))[c4] = v;
            }
        }
    }

#pragma unroll
    for (int off = 1; off <= 2; off <<= 1) {
#pragma unroll
        for (int q = 0; q < 4; q++) {
            float m2 = __shfl_xor_sync(0xffffffffu, pm[q], off);
            float s2 = __shfl_xor_sync(0xffffffffu, ps[q], off);
            comb(pm[q], ps[q], m2, s2);
        }
    }
    if ((lid & 3) == 0) {
#pragma unroll
        for (int q = 0; q < 4; q++) {
            int o = ob + (q >> 1) * 16 + (q & 1) * 8 + (lid >> 2);
            red_m[wid >> 2][o] = pm[q];
            red_s[wid >> 2][o] = ps[q];
        }
    }
    __syncthreads();
    if (tid < C) {
        float M = red_m[0][tid], S = red_s[0][tid];
        comb(M, S, red_m[1][tid], red_s[1][tid]);
        comb(M, S, red_m[2][tid], red_s[2][tid]);
        comb(M, S, red_m[3][tid], red_s[3][tid]);
        g_pm[(size_t)tid * NBLK + bid] = M;
        g_ps[(size_t)tid * NBLK + bid] = S;
    }
}

// ---------------- 5) combine softmax partials --------------------------------
__global__ void k_softmax_par() {
    int o = blockIdx.x;
    float M = -INFINITY, S = 0.f;
    for (int b = threadIdx.x; b < NBLK; b += 256)
        comb(M, S, g_pm[(size_t)o * NBLK + b], g_ps[(size_t)o * NBLK + b]);
#pragma unroll
    for (int off = 16; off; off >>= 1) {
        float m2 = __shfl_xor_sync(0xffffffffu, M, off);
        float s2 = __shfl_xor_sync(0xffffffffu, S, off);
        comb(M, S, m2, s2);
    }
    __shared__ float sm[8], ss[8];
    int wq = threadIdx.x >> 5, lane = threadIdx.x & 31;
    if (lane == 0) { sm[wq] = M; ss[wq] = S; }
    __syncthreads();
    if (threadIdx.x == 0) {
#pragma unroll
        for (int i = 1; i < 8; i++) comb(sm[0], ss[0], sm[i], ss[i]);
        g_max[o]  = sm[0];
        g_sinv[o] = 1.0f / ss[0];
    }
}

// ---------------- 6) final: thresholded exp + normalize ----------------------
__global__ void k_final2(float* __restrict__ out) {
    int base = blockIdx.x * 512 + threadIdx.x;
#pragma unroll
    for (int h = 0; h < 2; h++) {
        int f = base + h * 256;
        float4 v = ((const float4*)out)[f];
        int og = f & 31;
        float4 M = ((const float4*)g_max)[og];
        float4 I = ((const float4*)g_sinv)[og];
        float t0 = v.x - M.x, t1 = v.y - M.y, t2 = v.z - M.z, t3 = v.w - M.w;
        v.x = (t0 > -87.f) ? __expf(t0) * I.x : 0.f;
        v.y = (t1 > -87.f) ? __expf(t1) * I.y : 0.f;
        v.z = (t2 > -87.f) ? __expf(t2) * I.z : 0.f;
        v.w = (t3 > -87.f) ? __expf(t3) * I.w : 0.f;
        ((float4*)out)[f] = v;
    }
}

// ---------------- launcher ---------------------------------------------------
extern "C" void kernel_launch(void* const* d_in, const int* in_sizes, int n_in,
                              void* d_out, int out_size) {
    const float* x      = (const float*)d_in[0];
    const float* U      = (const float*)d_in[1];
    const float* coeffs = (const float*)d_in[2];
    float* out = (float*)d_out;

    cudaFuncSetAttribute(k_gemm1_mma, cudaFuncAttributeMaxDynamicSharedMemorySize,
                         G1_SM);
    cudaFuncSetAttribute(k_gemm3_p, cudaFuncAttributeMaxDynamicSharedMemorySize,
                         SM_TOT);

    k_gemm1_mma<<<NBLK, 512, G1_SM>>>(U, x);
    k_rsum<<<64, 256>>>();
    k_mixed_w<<<512, 256>>>(coeffs);
    k_gemm3_p<<<NBLK, 512, SM_TOT>>>(U, out);
    k_softmax_par<<<C, 256>>>();
    k_final2<<<N_TOK * C / 4 / 512, 256>>>(out);
}

// round 13
// speedup vs baseline: 1.3362x; 1.0154x over previous
#include <cuda_runtime.h>
#include <cuda_fp16.h>
#include <math.h>
#include <stdint.h>

#define N_TOK  100000
#define C      128
#define NT     128
#define NTILES ((N_TOK + NT - 1) / NT)            // 782  (GEMM2 tiles)
#define NBLK   148
#define CH     64
#define NCH    ((N_TOK + CH - 1) / CH)            // 1563 (GEMM1 chunks)

typedef unsigned long long ull;

// ---------------- scratch ----------------------------------------------------
__device__ float g_part[NBLK * C * C];
__device__ float g_spec[C * C];
__device__ float g_mixed[C * C];                 // mixed [o][k]
__device__ float g_pm[C * NBLK];
__device__ float g_ps[C * NBLK];
__device__ float g_max[C];
__device__ float g_sinv[C];

__device__ __forceinline__ void comb(float& m, float& s, float m2, float s2) {
    float M = fmaxf(m, m2);
    float S = 0.f;
    if (m  > -INFINITY) S += s  * __expf(m  - M);
    if (m2 > -INFINITY) S += s2 * __expf(m2 - M);
    m = M; s = S;
}

// ---------------- fp16 warp-MMA helpers --------------------------------------
__device__ __forceinline__ uint32_t smem_u32(const void* p) {
    uint32_t a;
    asm("{ .reg .u64 t; cvta.to.shared.u64 t, %1; cvt.u32.u64 %0, t; }"
        : "=r"(a) : "l"(p));
    return a;
}
__device__ __forceinline__ void ldsm4(uint32_t& r0, uint32_t& r1,
                                      uint32_t& r2, uint32_t& r3, uint32_t addr) {
    asm volatile("ldmatrix.sync.aligned.m8n8.x4.shared.b16 {%0,%1,%2,%3}, [%4];"
                 : "=r"(r0), "=r"(r1), "=r"(r2), "=r"(r3) : "r"(addr));
}
__device__ __forceinline__ void ldsm4t(uint32_t& r0, uint32_t& r1,
                                       uint32_t& r2, uint32_t& r3, uint32_t addr) {
    asm volatile("ldmatrix.sync.aligned.m8n8.x4.trans.shared.b16 {%0,%1,%2,%3}, [%4];"
                 : "=r"(r0), "=r"(r1), "=r"(r2), "=r"(r3) : "r"(addr));
}
__device__ __forceinline__ void mma_f16(float* d, const uint32_t* a,
                                        const uint32_t* b) {
    asm volatile(
        "mma.sync.aligned.m16n8k16.row.col.f32.f16.f16.f32 "
        "{%0,%1,%2,%3}, {%4,%5,%6,%7}, {%8,%9}, {%0,%1,%2,%3};"
        : "+f"(d[0]), "+f"(d[1]), "+f"(d[2]), "+f"(d[3])
        : "r"(a[0]), "r"(a[1]), "r"(a[2]), "r"(a[3]), "r"(b[0]), "r"(b[1]));
}
__device__ __forceinline__ uint32_t h2_bits(__half2 h) {
    union { __half2 h; uint32_t u; } c; c.h = h; return c.u;
}
__device__ __forceinline__ void split4(float4 v, uint2& H, uint2& L) {
    __half2 h01 = __float22half2_rn(make_float2(v.x, v.y));
    __half2 h23 = __float22half2_rn(make_float2(v.z, v.w));
    float2 b01 = __half22float2(h01);
    float2 b23 = __half22float2(h23);
    __half2 l01 = __float22half2_rn(make_float2(v.x - b01.x, v.y - b01.y));
    __half2 l23 = __float22half2_rn(make_float2(v.z - b23.x, v.w - b23.y));
    H.x = h2_bits(h01); H.y = h2_bits(h23);
    L.x = h2_bits(l01); L.y = h2_bits(l23);
}
#define ROWH 136
#define ROWB 272

// ---------------- 1) GEMM1: persistent fp16-split-3 MMA ----------------------
// spec[k=128][i=128] = sum_n U[n][k]*x[n][i]; MMA-K = n (trans ldmatrix loads)
#define G1_UH  0
#define G1_UL  17408
#define G1_XH  34816
#define G1_XL  52224
#define G1_RAW 69632
#define G1_SM  200704

__global__ void __launch_bounds__(512, 1) k_gemm1_mma(const float* __restrict__ U,
                                                      const float* __restrict__ x) {
    extern __shared__ char smem[];
    uint32_t sb = smem_u32(smem);
    int tid = threadIdx.x, wid = tid >> 5, lid = tid & 31;
    int bid = blockIdx.x;
    int kb = (wid & 3) * 32;
    int ib = (wid >> 2) * 32;

    int arow = (lid & 7) + ((lid >> 4) & 1) * 8;
    int acol = ((lid >> 3) & 1) * 8;
    int brow = (lid & 7) + ((lid >> 3) & 1) * 8;
    int bcol = ((lid >> 4) & 1) * 8;

    auto cp_chunk = [&](int ch, int buf) {
        int n0 = ch * CH;
        int nv = min(CH, N_TOK - n0);
#pragma unroll
        for (int i = 0; i < 4; i++) {
            int f = i * 512 + tid;
            int r = f >> 5, c4 = f & 31;
            int ok = (r < nv);
            const float* gu = U + (size_t)(n0 + (ok ? r : 0)) * C + 4 * c4;
            const float* gx = x + (size_t)(n0 + (ok ? r : 0)) * C + 4 * c4;
            uint32_t du = sb + G1_RAW + buf * 65536 + f * 16;
            int sz = ok ? 16 : 0;
            asm volatile("cp.async.cg.shared.global [%0], [%1], 16, %2;"
                         :: "r"(du), "l"(gu), "r"(sz) : "memory");
            asm volatile("cp.async.cg.shared.global [%0], [%1], 16, %2;"
                         :: "r"(du + 32768u), "l"(gx), "r"(sz) : "memory");
        }
        asm volatile("cp.async.commit_group;" ::: "memory");
    };

    float d[2][4][4];
#pragma unroll
    for (int mf = 0; mf < 2; mf++)
#pragma unroll
        for (int nf = 0; nf < 4; nf++)
#pragma unroll
            for (int q = 0; q < 4; q++) d[mf][nf][q] = 0.f;

    cp_chunk(bid, 0);
    int it = 0;
    for (int ch = bid; ch < NCH; ch += NBLK, it++) {
        int buf = it & 1;
        if (ch + NBLK < NCH) {
            cp_chunk(ch + NBLK, buf ^ 1);
            asm volatile("cp.async.wait_group 1;" ::: "memory");
        } else {
            asm volatile("cp.async.wait_group 0;" ::: "memory");
        }
        __syncthreads();

#pragma unroll
        for (int i = 0; i < 4; i++) {
            int f = i * 512 + tid;
            int r = f >> 5, c4 = f & 31;
            float4 vu = *(const float4*)(smem + G1_RAW + buf * 65536 + f * 16);
            float4 vx = *(const float4*)(smem + G1_RAW + buf * 65536 + 32768 + f * 16);
            uint2 H, L;
            split4(vu, H, L);
            *(uint2*)(smem + G1_UH + r * ROWB + 8 * c4) = H;
            *(uint2*)(smem + G1_UL + r * ROWB + 8 * c4) = L;
            split4(vx, H, L);
            *(uint2*)(smem + G1_XH + r * ROWB + 8 * c4) = H;
            *(uint2*)(smem + G1_XL + r * ROWB + 8 * c4) = L;
        }
        __syncthreads();

#pragma unroll
        for (int pass = 0; pass < 3; pass++) {
            uint32_t aB = sb + ((pass == 2) ? G1_UL : G1_UH);
            uint32_t bB = sb + ((pass == 1) ? G1_XL : G1_XH);
#pragma unroll
            for (int ks = 0; ks < 4; ks++) {
                int t0 = 16 * ks;
                uint32_t a[2][4], bq[2][4];
#pragma unroll
                for (int mf = 0; mf < 2; mf++) {
                    uint32_t addr = aB +
                        ((t0 + arow) * ROWH + kb + mf * 16 + acol) * 2;
                    ldsm4t(a[mf][0], a[mf][1], a[mf][2], a[mf][3], addr);
                }
#pragma unroll
                for (int p4 = 0; p4 < 2; p4++) {
                    uint32_t addr = bB +
                        ((t0 + brow) * ROWH + ib + p4 * 16 + bcol) * 2;
                    ldsm4t(bq[p4][0], bq[p4][1], bq[p4][2], bq[p4][3], addr);
                }
#pragma unroll
                for (int mf = 0; mf < 2; mf++)
#pragma unroll
                    for (int nf = 0; nf < 4; nf++)
                        mma_f16(d[mf][nf], a[mf], &bq[nf >> 1][2 * (nf & 1)]);
            }
        }
    }

    float* dst = g_part + (size_t)bid * (C * C);
#pragma unroll
    for (int mf = 0; mf < 2; mf++)
#pragma unroll
        for (int nf = 0; nf < 4; nf++) {
            int row = kb + mf * 16 + (lid >> 2);
            int col = ib + nf * 8 + 2 * (lid & 3);
            *(float2*)&dst[row * C + col] =
                make_float2(d[mf][nf][0], d[mf][nf][1]);
            *(float2*)&dst[(row + 8) * C + col] =
                make_float2(d[mf][nf][2], d[mf][nf][3]);
        }
}

// ---------------- 2) reduce partials -> g_spec -------------------------------
__global__ void k_rsum() {
    int j = blockIdx.x * 256 + threadIdx.x;
    float s0 = 0.f, s1 = 0.f, s2 = 0.f, s3 = 0.f;
#pragma unroll 1
    for (int b = 0; b < NBLK; b += 4) {
        s0 += g_part[(b + 0) * (C * C) + j];
        s1 += g_part[(b + 1) * (C * C) + j];
        s2 += g_part[(b + 2) * (C * C) + j];
        s3 += g_part[(b + 3) * (C * C) + j];
    }
    g_spec[j] = (s0 + s1) + (s2 + s3);
}

// ---------------- 3) mixed -> g_mixed[o][k] ----------------------------------
__global__ void __launch_bounds__(256) k_mixed_w(const float* __restrict__ coeffs) {
    int gw   = blockIdx.x * 8 + (threadIdx.x >> 5);
    int lane = threadIdx.x & 31;
    int o = gw >> 5, k0 = (gw & 31) * 4;
    float s[4];
#pragma unroll
    for (int kk = 0; kk < 4; kk++) {
        int k = k0 + kk;
        float4 a  = ((const float4*)(coeffs + (((size_t)o * C + k) << 7)))[lane];
        float4 bv = ((const float4*)(g_spec + (k << 7)))[lane];
        s[kk] = a.x * bv.x + a.y * bv.y + a.z * bv.z + a.w * bv.w;
    }
#pragma unroll
    for (int off = 16; off; off >>= 1)
#pragma unroll
        for (int kk = 0; kk < 4; kk++)
            s[kk] += __shfl_xor_sync(0xffffffffu, s[kk], off);
    if (lane == 0) {
#pragma unroll
        for (int kk = 0; kk < 4; kk++) g_mixed[(size_t)o * C + k0 + kk] = s[kk];
    }
}

// ---------------- 4) GEMM2: quad-partitioned persistent fp16-split-3 MMA -----
// Four independent 128-thread pipelines per block. Quad q owns n-rows
// [32q,32q+32): its raw slice, its B_HI/B_LO rows, and a staging area that
// ALIASES ONLY ITS OWN B rows (hi chunk rows 0-15, lo chunk rows 16-31) so
// every in-loop hazard is quad-internal -> named quad barriers only.
#define A_HI 0
#define A_LO 34816
#define B_HI 69632
#define B_LO 104448
#define RAWB 139264
#define SM_TOT 204800
#define SUM_THR (-15.0f)
#define QCH 8704                  // per-quad B chunk bytes (32 rows * 272)
#define SROW 528                  // staging row stride bytes (132 floats)

__global__ void __launch_bounds__(512, 1) k_gemm3_p(const float* __restrict__ U,
                                                    float* __restrict__ out) {
    extern __shared__ char smem[];
    uint32_t sb = smem_u32(smem);
    __shared__ float red_m[4][C], red_s[4][C];
    int tid = threadIdx.x, wid = tid >> 5, lid = tid & 31;
    int bid = blockIdx.x;
    int quad = tid >> 7;                // 0..3  (n-slice owner)
    int qtid = tid & 127;
    int ob  = (wid & 3) * 32;           // warp o-base
    int nbw = quad * 32;                // quad n-base

    int arow_l = (lid & 7) + ((lid >> 3) & 1) * 8;
    int acol_l = ((lid >> 4) & 1) * 8;
    int brow_l = (lid & 7) + ((lid >> 4) & 1) * 8;
    int bcol_l = ((lid >> 3) & 1) * 8;

#define QBAR() asm volatile("bar.sync %0, 128;" :: "r"(1 + quad) : "memory")
    // quad-private staging pointer: row rr (0..31), float index o (0..131)
    auto stg_ptr = [&](int rr, int o) -> float* {
        int base = ((rr & 16) ? B_LO : B_HI) + QCH * quad + (rr & 15) * SROW;
        return (float*)(smem + base) + o;
    };

    // quad-local prefetch of its 32 rows of a tile
    auto cp_tile = [&](int t) {
        int n0 = t * NT;
        int nvalid = min(NT, N_TOK - n0);
#pragma unroll
        for (int i = 0; i < 8; i++) {
            int f = i * 128 + qtid;             // 0..1023 within quad
            int r = nbw + (f >> 5), c4 = f & 31;
            int ok = (r < nvalid);
            const float* g = U + (size_t)(n0 + (ok ? r : 0)) * C + 4 * c4;
            uint32_t dst = sb + RAWB + (r * 32 + c4) * 16;
            int sz = ok ? 16 : 0;
            asm volatile("cp.async.cg.shared.global [%0], [%1], 16, %2;"
                         :: "r"(dst), "l"(g), "r"(sz) : "memory");
        }
        asm volatile("cp.async.commit_group;" ::: "memory");
    };

    if (bid < NTILES) cp_tile(bid);
    // A fill (block-wide, once)
#pragma unroll
    for (int i = 0; i < 8; i++) {
        int f = i * 512 + tid;
        int r = f >> 5, c4 = f & 31;
        float4 v = ((const float4*)(g_mixed + (size_t)r * C))[c4];
        uint2 H, L;
        split4(v, H, L);
        *(uint2*)(smem + A_HI + r * ROWB + 8 * c4) = H;
        *(uint2*)(smem + A_LO + r * ROWB + 8 * c4) = L;
    }
    __syncthreads();                     // A visible to all quads

    float pm[4] = { -INFINITY, -INFINITY, -INFINITY, -INFINITY };
    float ps[4] = { 0.f, 0.f, 0.f, 0.f };

    for (int t = bid; t < NTILES; t += NBLK) {
        int n0 = t * NT;
        int nvalid = min(NT, N_TOK - n0);

        asm volatile("cp.async.wait_group 0;" ::: "memory");
        QBAR();                          // raw visible; prev stg/store done

        // convert quad's raw rows -> its B hi/lo rows (overwrites its stg)
#pragma unroll
        for (int i = 0; i < 8; i++) {
            int f = i * 128 + qtid;
            int r = nbw + (f >> 5), c4 = f & 31;
            float4 v = *(const float4*)(smem + RAWB + (r * 32 + c4) * 16);
            uint2 H, L;
            split4(v, H, L);
            *(uint2*)(smem + B_HI + r * ROWB + 8 * c4) = H;
            *(uint2*)(smem + B_LO + r * ROWB + 8 * c4) = L;
        }
        QBAR();                          // B ready; raw consumed

        if (t + NBLK < NTILES) cp_tile(t + NBLK);

        float d[2][4][4];
#pragma unroll
        for (int mf = 0; mf < 2; mf++)
#pragma unroll
            for (int nf = 0; nf < 4; nf++)
#pragma unroll
                for (int q = 0; q < 4; q++) d[mf][nf][q] = 0.f;

#pragma unroll
        for (int pass = 0; pass < 3; pass++) {
            uint32_t aB = sb + ((pass == 2) ? A_LO : A_HI);
            uint32_t bB = sb + ((pass == 1) ? B_LO : B_HI);
#pragma unroll
            for (int ks = 0; ks < 8; ks++) {
                int k0 = 16 * ks;
                uint32_t a[2][4], bq[2][4];
#pragma unroll
                for (int mf = 0; mf < 2; mf++) {
                    uint32_t addr = aB +
                        ((ob + mf * 16 + arow_l) * ROWH + k0 + acol_l) * 2;
                    ldsm4(a[mf][0], a[mf][1], a[mf][2], a[mf][3], addr);
                }
#pragma unroll
                for (int p4 = 0; p4 < 2; p4++) {
                    uint32_t addr = bB +
                        ((nbw + p4 * 16 + brow_l) * ROWH + k0 + bcol_l) * 2;
                    ldsm4(bq[p4][0], bq[p4][1], bq[p4][2], bq[p4][3], addr);
                }
#pragma unroll
                for (int mf = 0; mf < 2; mf++)
#pragma unroll
                    for (int nf = 0; nf < 4; nf++)
                        mma_f16(d[mf][nf], a[mf], &bq[nf >> 1][2 * (nf & 1)]);
            }
        }
        QBAR();                          // quad MMA reads done before staging

        // softmax partials (thresholded exp; padded logits = 0 vanish)
#pragma unroll
        for (int mf = 0; mf < 2; mf++)
#pragma unroll
            for (int h = 0; h < 2; h++) {
                int q = 2 * mf + h;
                float mt = -INFINITY;
#pragma unroll
                for (int nf = 0; nf < 4; nf++)
                    mt = fmaxf(mt, fmaxf(d[mf][nf][2 * h], d[mf][nf][2 * h + 1]));
                if (mt > pm[q]) {
                    ps[q] *= __expf(pm[q] - mt);
                    pm[q] = mt;
                }
                float m = pm[q];
#pragma unroll
                for (int nf = 0; nf < 4; nf++) {
                    float t0 = d[mf][nf][2 * h] - m;
                    float t1 = d[mf][nf][2 * h + 1] - m;
                    if (t0 > SUM_THR) ps[q] += __expf(t0);
                    if (t1 > SUM_THR) ps[q] += __expf(t1);
                }
            }

        // stage logits [rr][o] into the quad's OWN retired B rows
#pragma unroll
        for (int mf = 0; mf < 2; mf++)
#pragma unroll
            for (int nf = 0; nf < 4; nf++) {
                int rr = nf * 8 + 2 * (lid & 3);
                int o  = ob + mf * 16 + (lid >> 2);
                *stg_ptr(rr,     o)     = d[mf][nf][0];
                *stg_ptr(rr + 1, o)     = d[mf][nf][1];
                *stg_ptr(rr,     o + 8) = d[mf][nf][2];
                *stg_ptr(rr + 1, o + 8) = d[mf][nf][3];
            }
        QBAR();                          // staging complete within quad

        // coalesced logit store (quad rows)
#pragma unroll
        for (int i = 0; i < 8; i++) {
            int f = i * 128 + qtid;
            int rr = f >> 5, c4 = f & 31;
            int r = nbw + rr;
            if (r < nvalid) {
                float4 v = *(const float4*)stg_ptr(rr, 4 * c4);
                ((float4*)(out + (size_t)(n0 + r) * C))[c4] = v;
            }
        }
    }

    // ---- per-block softmax partials ----
#pragma unroll
    for (int off = 1; off <= 2; off <<= 1) {
#pragma unroll
        for (int q = 0; q < 4; q++) {
            float m2 = __shfl_xor_sync(0xffffffffu, pm[q], off);
            float s2 = __shfl_xor_sync(0xffffffffu, ps[q], off);
            comb(pm[q], ps[q], m2, s2);
        }
    }
    if ((lid & 3) == 0) {
#pragma unroll
        for (int q = 0; q < 4; q++) {
            int o = ob + (q >> 1) * 16 + (q & 1) * 8 + (lid >> 2);
            red_m[quad][o] = pm[q];
            red_s[quad][o] = ps[q];
        }
    }
    __syncthreads();
    if (tid < C) {
        float M = red_m[0][tid], S = red_s[0][tid];
        comb(M, S, red_m[1][tid], red_s[1][tid]);
        comb(M, S, red_m[2][tid], red_s[2][tid]);
        comb(M, S, red_m[3][tid], red_s[3][tid]);
        g_pm[(size_t)tid * NBLK + bid] = M;
        g_ps[(size_t)tid * NBLK + bid] = S;
    }
#undef QBAR
}

// ---------------- 5) combine softmax partials --------------------------------
__global__ void k_softmax_par() {
    int o = blockIdx.x;
    float M = -INFINITY, S = 0.f;
    for (int b = threadIdx.x; b < NBLK; b += 256)
        comb(M, S, g_pm[(size_t)o * NBLK + b], g_ps[(size_t)o * NBLK + b]);
#pragma unroll
    for (int off = 16; off; off >>= 1) {
        float m2 = __shfl_xor_sync(0xffffffffu, M, off);
        float s2 = __shfl_xor_sync(0xffffffffu, S, off);
        comb(M, S, m2, s2);
    }
    __shared__ float sm[8], ss[8];
    int wq = threadIdx.x >> 5, lane = threadIdx.x & 31;
    if (lane == 0) { sm[wq] = M; ss[wq] = S; }
    __syncthreads();
    if (threadIdx.x == 0) {
#pragma unroll
        for (int i = 1; i < 8; i++) comb(sm[0], ss[0], sm[i], ss[i]);
        g_max[o]  = sm[0];
        g_sinv[o] = 1.0f / ss[0];
    }
}

// ---------------- 6) final: thresholded exp + normalize ----------------------
__global__ void k_final2(float* __restrict__ out) {
    int base = blockIdx.x * 512 + threadIdx.x;
#pragma unroll
    for (int h = 0; h < 2; h++) {
        int f = base + h * 256;
        float4 v = ((const float4*)out)[f];
        int og = f & 31;
        float4 M = ((const float4*)g_max)[og];
        float4 I = ((const float4*)g_sinv)[og];
        float t0 = v.x - M.x, t1 = v.y - M.y, t2 = v.z - M.z, t3 = v.w - M.w;
        v.x = (t0 > -87.f) ? __expf(t0) * I.x : 0.f;
        v.y = (t1 > -87.f) ? __expf(t1) * I.y : 0.f;
        v.z = (t2 > -87.f) ? __expf(t2) * I.z : 0.f;
        v.w = (t3 > -87.f) ? __expf(t3) * I.w : 0.f;
        ((float4*)out)[f] = v;
    }
}

// ---------------- launcher ---------------------------------------------------
extern "C" void kernel_launch(void* const* d_in, const int* in_sizes, int n_in,
                              void* d_out, int out_size) {
    const float* x      = (const float*)d_in[0];
    const float* U      = (const float*)d_in[1];
    const float* coeffs = (const float*)d_in[2];
    float* out = (float*)d_out;

    cudaFuncSetAttribute(k_gemm1_mma, cudaFuncAttributeMaxDynamicSharedMemorySize,
                         G1_SM);
    cudaFuncSetAttribute(k_gemm3_p, cudaFuncAttributeMaxDynamicSharedMemorySize,
                         SM_TOT);

    k_gemm1_mma<<<NBLK, 512, G1_SM>>>(U, x);
    k_rsum<<<64, 256>>>();
    k_mixed_w<<<512, 256>>>(coeffs);
    k_gemm3_p<<<NBLK, 512, SM_TOT>>>(U, out);
    k_softmax_par<<<C, 256>>>();
    k_final2<<<N_TOK * C / 4 / 512, 256>>>(out);
}

// round 14
// speedup vs baseline: 1.6344x; 1.2232x over previous
#include <cuda_runtime.h>
#include <cuda_fp16.h>
#include <math.h>
#include <stdint.h>

#define N_TOK  100000
#define C      128
#define NT     128
#define NTILES ((N_TOK + NT - 1) / NT)            // 782  (GEMM2 tiles)
#define NBLK   148
#define CH     64
#define NCH    ((N_TOK + CH - 1) / CH)            // 1563 (GEMM1 chunks)

typedef unsigned long long ull;

// ---------------- scratch ----------------------------------------------------
__device__ float g_part[NBLK * C * C];
__device__ float g_spec[C * C];
__device__ float g_mixed[C * C];                 // mixed [o][k]
__device__ float g_pm[C * NBLK];
__device__ float g_ps[C * NBLK];
__device__ float g_max[C];
__device__ float g_sinv[C];

__device__ __forceinline__ void comb(float& m, float& s, float m2, float s2) {
    float M = fmaxf(m, m2);
    float S = 0.f;
    if (m  > -INFINITY) S += s  * __expf(m  - M);
    if (m2 > -INFINITY) S += s2 * __expf(m2 - M);
    m = M; s = S;
}

// ---------------- fp16 warp-MMA helpers --------------------------------------
__device__ __forceinline__ uint32_t smem_u32(const void* p) {
    uint32_t a;
    asm("{ .reg .u64 t; cvta.to.shared.u64 t, %1; cvt.u32.u64 %0, t; }"
        : "=r"(a) : "l"(p));
    return a;
}
__device__ __forceinline__ void ldsm4(uint32_t& r0, uint32_t& r1,
                                      uint32_t& r2, uint32_t& r3, uint32_t addr) {
    asm volatile("ldmatrix.sync.aligned.m8n8.x4.shared.b16 {%0,%1,%2,%3}, [%4];"
                 : "=r"(r0), "=r"(r1), "=r"(r2), "=r"(r3) : "r"(addr));
}
__device__ __forceinline__ void ldsm4t(uint32_t& r0, uint32_t& r1,
                                       uint32_t& r2, uint32_t& r3, uint32_t addr) {
    asm volatile("ldmatrix.sync.aligned.m8n8.x4.trans.shared.b16 {%0,%1,%2,%3}, [%4];"
                 : "=r"(r0), "=r"(r1), "=r"(r2), "=r"(r3) : "r"(addr));
}
__device__ __forceinline__ void mma_f16(float* d, const uint32_t* a,
                                        const uint32_t* b) {
    asm volatile(
        "mma.sync.aligned.m16n8k16.row.col.f32.f16.f16.f32 "
        "{%0,%1,%2,%3}, {%4,%5,%6,%7}, {%8,%9}, {%0,%1,%2,%3};"
        : "+f"(d[0]), "+f"(d[1]), "+f"(d[2]), "+f"(d[3])
        : "r"(a[0]), "r"(a[1]), "r"(a[2]), "r"(a[3]), "r"(b[0]), "r"(b[1]));
}
__device__ __forceinline__ uint32_t h2_bits(__half2 h) {
    union { __half2 h; uint32_t u; } c; c.h = h; return c.u;
}
__device__ __forceinline__ void split4(float4 v, uint2& H, uint2& L) {
    __half2 h01 = __float22half2_rn(make_float2(v.x, v.y));
    __half2 h23 = __float22half2_rn(make_float2(v.z, v.w));
    float2 b01 = __half22float2(h01);
    float2 b23 = __half22float2(h23);
    __half2 l01 = __float22half2_rn(make_float2(v.x - b01.x, v.y - b01.y));
    __half2 l23 = __float22half2_rn(make_float2(v.z - b23.x, v.w - b23.y));
    H.x = h2_bits(h01); H.y = h2_bits(h23);
    L.x = h2_bits(l01); L.y = h2_bits(l23);
}
#define ROWH 136
#define ROWB 272

// ---------------- 1) GEMM1: persistent fp16-split, FUSED 3-product loop ------
// spec[k=128][i=128] = sum_n U[n][k]*x[n][i]; MMA-K = n (trans ldmatrix loads)
#define G1_UH  0
#define G1_UL  17408
#define G1_XH  34816
#define G1_XL  52224
#define G1_RAW 69632
#define G1_SM  200704

__global__ void __launch_bounds__(512, 1) k_gemm1_mma(const float* __restrict__ U,
                                                      const float* __restrict__ x) {
    extern __shared__ char smem[];
    uint32_t sb = smem_u32(smem);
    int tid = threadIdx.x, wid = tid >> 5, lid = tid & 31;
    int bid = blockIdx.x;
    int kb = (wid & 3) * 32;
    int ib = (wid >> 2) * 32;

    int arow = (lid & 7) + ((lid >> 4) & 1) * 8;
    int acol = ((lid >> 3) & 1) * 8;
    int brow = (lid & 7) + ((lid >> 3) & 1) * 8;
    int bcol = ((lid >> 4) & 1) * 8;

    auto cp_chunk = [&](int ch, int buf) {
        int n0 = ch * CH;
        int nv = min(CH, N_TOK - n0);
#pragma unroll
        for (int i = 0; i < 4; i++) {
            int f = i * 512 + tid;
            int r = f >> 5, c4 = f & 31;
            int ok = (r < nv);
            const float* gu = U + (size_t)(n0 + (ok ? r : 0)) * C + 4 * c4;
            const float* gx = x + (size_t)(n0 + (ok ? r : 0)) * C + 4 * c4;
            uint32_t du = sb + G1_RAW + buf * 65536 + f * 16;
            int sz = ok ? 16 : 0;
            asm volatile("cp.async.cg.shared.global [%0], [%1], 16, %2;"
                         :: "r"(du), "l"(gu), "r"(sz) : "memory");
            asm volatile("cp.async.cg.shared.global [%0], [%1], 16, %2;"
                         :: "r"(du + 32768u), "l"(gx), "r"(sz) : "memory");
        }
        asm volatile("cp.async.commit_group;" ::: "memory");
    };

    float d[2][4][4];
#pragma unroll
    for (int mf = 0; mf < 2; mf++)
#pragma unroll
        for (int nf = 0; nf < 4; nf++)
#pragma unroll
            for (int q = 0; q < 4; q++) d[mf][nf][q] = 0.f;

    cp_chunk(bid, 0);
    int it = 0;
    for (int ch = bid; ch < NCH; ch += NBLK, it++) {
        int buf = it & 1;
        if (ch + NBLK < NCH) {
            cp_chunk(ch + NBLK, buf ^ 1);
            asm volatile("cp.async.wait_group 1;" ::: "memory");
        } else {
            asm volatile("cp.async.wait_group 0;" ::: "memory");
        }
        __syncthreads();

#pragma unroll
        for (int i = 0; i < 4; i++) {
            int f = i * 512 + tid;
            int r = f >> 5, c4 = f & 31;
            float4 vu = *(const float4*)(smem + G1_RAW + buf * 65536 + f * 16);
            float4 vx = *(const float4*)(smem + G1_RAW + buf * 65536 + 32768 + f * 16);
            uint2 H, L;
            split4(vu, H, L);
            *(uint2*)(smem + G1_UH + r * ROWB + 8 * c4) = H;
            *(uint2*)(smem + G1_UL + r * ROWB + 8 * c4) = L;
            split4(vx, H, L);
            *(uint2*)(smem + G1_XH + r * ROWB + 8 * c4) = H;
            *(uint2*)(smem + G1_XL + r * ROWB + 8 * c4) = L;
        }
        __syncthreads();

        // fused 3-product loop: per kstep load u_hi/u_lo once, x_hi/x_lo once
#pragma unroll
        for (int ks = 0; ks < 4; ks++) {
            int t0 = 16 * ks;
            uint32_t uh[2][4], ul[2][4];
#pragma unroll
            for (int mf = 0; mf < 2; mf++) {
                uint32_t off = ((t0 + arow) * ROWH + kb + mf * 16 + acol) * 2;
                ldsm4t(uh[mf][0], uh[mf][1], uh[mf][2], uh[mf][3],
                       sb + G1_UH + off);
                ldsm4t(ul[mf][0], ul[mf][1], ul[mf][2], ul[mf][3],
                       sb + G1_UL + off);
            }
#pragma unroll
            for (int p4 = 0; p4 < 2; p4++) {
                uint32_t off = ((t0 + brow) * ROWH + ib + p4 * 16 + bcol) * 2;
                uint32_t xh[4], xl[4];
                ldsm4t(xh[0], xh[1], xh[2], xh[3], sb + G1_XH + off);
                ldsm4t(xl[0], xl[1], xl[2], xl[3], sb + G1_XL + off);
#pragma unroll
                for (int mf = 0; mf < 2; mf++)
#pragma unroll
                    for (int n2 = 0; n2 < 2; n2++) {
                        float* dd = d[mf][2 * p4 + n2];
                        mma_f16(dd, uh[mf], &xh[2 * n2]);
                        mma_f16(dd, uh[mf], &xl[2 * n2]);
                        mma_f16(dd, ul[mf], &xh[2 * n2]);
                    }
            }
        }
    }

    float* dst = g_part + (size_t)bid * (C * C);
#pragma unroll
    for (int mf = 0; mf < 2; mf++)
#pragma unroll
        for (int nf = 0; nf < 4; nf++) {
            int row = kb + mf * 16 + (lid >> 2);
            int col = ib + nf * 8 + 2 * (lid & 3);
            *(float2*)&dst[row * C + col] =
                make_float2(d[mf][nf][0], d[mf][nf][1]);
            *(float2*)&dst[(row + 8) * C + col] =
                make_float2(d[mf][nf][2], d[mf][nf][3]);
        }
}

// ---------------- 2) reduce partials -> g_spec -------------------------------
__global__ void k_rsum() {
    int j = blockIdx.x * 256 + threadIdx.x;
    float s0 = 0.f, s1 = 0.f, s2 = 0.f, s3 = 0.f;
#pragma unroll 1
    for (int b = 0; b < NBLK; b += 4) {
        s0 += g_part[(b + 0) * (C * C) + j];
        s1 += g_part[(b + 1) * (C * C) + j];
        s2 += g_part[(b + 2) * (C * C) + j];
        s3 += g_part[(b + 3) * (C * C) + j];
    }
    g_spec[j] = (s0 + s1) + (s2 + s3);
}

// ---------------- 3) mixed -> g_mixed[o][k] ----------------------------------
__global__ void __launch_bounds__(256) k_mixed_w(const float* __restrict__ coeffs) {
    int gw   = blockIdx.x * 8 + (threadIdx.x >> 5);
    int lane = threadIdx.x & 31;
    int o = gw >> 5, k0 = (gw & 31) * 4;
    float s[4];
#pragma unroll
    for (int kk = 0; kk < 4; kk++) {
        int k = k0 + kk;
        float4 a  = ((const float4*)(coeffs + (((size_t)o * C + k) << 7)))[lane];
        float4 bv = ((const float4*)(g_spec + (k << 7)))[lane];
        s[kk] = a.x * bv.x + a.y * bv.y + a.z * bv.z + a.w * bv.w;
    }
#pragma unroll
    for (int off = 16; off; off >>= 1)
#pragma unroll
        for (int kk = 0; kk < 4; kk++)
            s[kk] += __shfl_xor_sync(0xffffffffu, s[kk], off);
    if (lane == 0) {
#pragma unroll
        for (int kk = 0; kk < 4; kk++) g_mixed[(size_t)o * C + k0 + kk] = s[kk];
    }
}

// ---------------- 4) GEMM2: quad-partitioned, FUSED 3-product loop -----------
#define A_HI 0
#define A_LO 34816
#define B_HI 69632
#define B_LO 104448
#define RAWB 139264
#define SM_TOT 204800
#define SUM_THR (-15.0f)
#define QCH 8704                  // per-quad B chunk bytes (32 rows * 272)
#define SROW 528                  // staging row stride bytes (132 floats)

__global__ void __launch_bounds__(512, 1) k_gemm3_p(const float* __restrict__ U,
                                                    float* __restrict__ out) {
    extern __shared__ char smem[];
    uint32_t sb = smem_u32(smem);
    __shared__ float red_m[4][C], red_s[4][C];
    int tid = threadIdx.x, wid = tid >> 5, lid = tid & 31;
    int bid = blockIdx.x;
    int quad = tid >> 7;                // 0..3  (n-slice owner)
    int qtid = tid & 127;
    int ob  = (wid & 3) * 32;           // warp o-base
    int nbw = quad * 32;                // quad n-base

    int arow_l = (lid & 7) + ((lid >> 3) & 1) * 8;
    int acol_l = ((lid >> 4) & 1) * 8;
    int brow_l = (lid & 7) + ((lid >> 4) & 1) * 8;
    int bcol_l = ((lid >> 3) & 1) * 8;

#define QBAR() asm volatile("bar.sync %0, 128;" :: "r"(1 + quad) : "memory")
    auto stg_ptr = [&](int rr, int o) -> float* {
        int base = ((rr & 16) ? B_LO : B_HI) + QCH * quad + (rr & 15) * SROW;
        return (float*)(smem + base) + o;
    };

    auto cp_tile = [&](int t) {
        int n0 = t * NT;
        int nvalid = min(NT, N_TOK - n0);
#pragma unroll
        for (int i = 0; i < 8; i++) {
            int f = i * 128 + qtid;
            int r = nbw + (f >> 5), c4 = f & 31;
            int ok = (r < nvalid);
            const float* g = U + (size_t)(n0 + (ok ? r : 0)) * C + 4 * c4;
            uint32_t dst = sb + RAWB + (r * 32 + c4) * 16;
            int sz = ok ? 16 : 0;
            asm volatile("cp.async.cg.shared.global [%0], [%1], 16, %2;"
                         :: "r"(dst), "l"(g), "r"(sz) : "memory");
        }
        asm volatile("cp.async.commit_group;" ::: "memory");
    };

    if (bid < NTILES) cp_tile(bid);
#pragma unroll
    for (int i = 0; i < 8; i++) {
        int f = i * 512 + tid;
        int r = f >> 5, c4 = f & 31;
        float4 v = ((const float4*)(g_mixed + (size_t)r * C))[c4];
        uint2 H, L;
        split4(v, H, L);
        *(uint2*)(smem + A_HI + r * ROWB + 8 * c4) = H;
        *(uint2*)(smem + A_LO + r * ROWB + 8 * c4) = L;
    }
    __syncthreads();                     // A visible to all quads

    float pm[4] = { -INFINITY, -INFINITY, -INFINITY, -INFINITY };
    float ps[4] = { 0.f, 0.f, 0.f, 0.f };

    for (int t = bid; t < NTILES; t += NBLK) {
        int n0 = t * NT;
        int nvalid = min(NT, N_TOK - n0);

        asm volatile("cp.async.wait_group 0;" ::: "memory");
        QBAR();                          // raw visible; prev stg/store done

#pragma unroll
        for (int i = 0; i < 8; i++) {
            int f = i * 128 + qtid;
            int r = nbw + (f >> 5), c4 = f & 31;
            float4 v = *(const float4*)(smem + RAWB + (r * 32 + c4) * 16);
            uint2 H, L;
            split4(v, H, L);
            *(uint2*)(smem + B_HI + r * ROWB + 8 * c4) = H;
            *(uint2*)(smem + B_LO + r * ROWB + 8 * c4) = L;
        }
        QBAR();                          // B ready; raw consumed

        if (t + NBLK < NTILES) cp_tile(t + NBLK);

        float d[2][4][4];
#pragma unroll
        for (int mf = 0; mf < 2; mf++)
#pragma unroll
            for (int nf = 0; nf < 4; nf++)
#pragma unroll
                for (int q = 0; q < 4; q++) d[mf][nf][q] = 0.f;

        // fused 3-product loop: a_hi/a_lo resident per kstep, b transient
#pragma unroll
        for (int ks = 0; ks < 8; ks++) {
            int k0 = 16 * ks;
            uint32_t ah[2][4], al[2][4];
#pragma unroll
            for (int mf = 0; mf < 2; mf++) {
                uint32_t off = ((ob + mf * 16 + arow_l) * ROWH + k0 + acol_l) * 2;
                ldsm4(ah[mf][0], ah[mf][1], ah[mf][2], ah[mf][3], sb + A_HI + off);
                ldsm4(al[mf][0], al[mf][1], al[mf][2], al[mf][3], sb + A_LO + off);
            }
#pragma unroll
            for (int p4 = 0; p4 < 2; p4++) {
                uint32_t off = ((nbw + p4 * 16 + brow_l) * ROWH + k0 + bcol_l) * 2;
                uint32_t bh[4], bl[4];
                ldsm4(bh[0], bh[1], bh[2], bh[3], sb + B_HI + off);
                ldsm4(bl[0], bl[1], bl[2], bl[3], sb + B_LO + off);
#pragma unroll
                for (int mf = 0; mf < 2; mf++)
#pragma unroll
                    for (int n2 = 0; n2 < 2; n2++) {
                        float* dd = d[mf][2 * p4 + n2];
                        mma_f16(dd, ah[mf], &bh[2 * n2]);
                        mma_f16(dd, ah[mf], &bl[2 * n2]);
                        mma_f16(dd, al[mf], &bh[2 * n2]);
                    }
            }
        }
        QBAR();                          // quad MMA reads done before staging

        // softmax partials (thresholded exp; padded logits = 0 vanish)
#pragma unroll
        for (int mf = 0; mf < 2; mf++)
#pragma unroll
            for (int h = 0; h < 2; h++) {
                int q = 2 * mf + h;
                float mt = -INFINITY;
#pragma unroll
                for (int nf = 0; nf < 4; nf++)
                    mt = fmaxf(mt, fmaxf(d[mf][nf][2 * h], d[mf][nf][2 * h + 1]));
                if (mt > pm[q]) {
                    ps[q] *= __expf(pm[q] - mt);
                    pm[q] = mt;
                }
                float m = pm[q];
#pragma unroll
                for (int nf = 0; nf < 4; nf++) {
                    float t0 = d[mf][nf][2 * h] - m;
                    float t1 = d[mf][nf][2 * h + 1] - m;
                    if (t0 > SUM_THR) ps[q] += __expf(t0);
                    if (t1 > SUM_THR) ps[q] += __expf(t1);
                }
            }

        // stage logits [rr][o] into the quad's OWN retired B rows
#pragma unroll
        for (int mf = 0; mf < 2; mf++)
#pragma unroll
            for (int nf = 0; nf < 4; nf++) {
                int rr = nf * 8 + 2 * (lid & 3);
                int o  = ob + mf * 16 + (lid >> 2);
                *stg_ptr(rr,     o)     = d[mf][nf][0];
                *stg_ptr(rr + 1, o)     = d[mf][nf][1];
                *stg_ptr(rr,     o + 8) = d[mf][nf][2];
                *stg_ptr(rr + 1, o + 8) = d[mf][nf][3];
            }
        QBAR();                          // staging complete within quad

        // coalesced logit store (quad rows)
#pragma unroll
        for (int i = 0; i < 8; i++) {
            int f = i * 128 + qtid;
            int rr = f >> 5, c4 = f & 31;
            int r = nbw + rr;
            if (r < nvalid) {
                float4 v = *(const float4*)stg_ptr(rr, 4 * c4);
                ((float4*)(out + (size_t)(n0 + r) * C))[c4] = v;
            }
        }
    }

    // ---- per-block softmax partials ----
#pragma unroll
    for (int off = 1; off <= 2; off <<= 1) {
#pragma unroll
        for (int q = 0; q < 4; q++) {
            float m2 = __shfl_xor_sync(0xffffffffu, pm[q], off);
            float s2 = __shfl_xor_sync(0xffffffffu, ps[q], off);
            comb(pm[q], ps[q], m2, s2);
        }
    }
    if ((lid & 3) == 0) {
#pragma unroll
        for (int q = 0; q < 4; q++) {
            int o = ob + (q >> 1) * 16 + (q & 1) * 8 + (lid >> 2);
            red_m[quad][o] = pm[q];
            red_s[quad][o] = ps[q];
        }
    }
    __syncthreads();
    if (tid < C) {
        float M = red_m[0][tid], S = red_s[0][tid];
        comb(M, S, red_m[1][tid], red_s[1][tid]);
        comb(M, S, red_m[2][tid], red_s[2][tid]);
        comb(M, S, red_m[3][tid], red_s[3][tid]);
        g_pm[(size_t)tid * NBLK + bid] = M;
        g_ps[(size_t)tid * NBLK + bid] = S;
    }
#undef QBAR
}

// ---------------- 5) combine softmax partials --------------------------------
__global__ void k_softmax_par() {
    int o = blockIdx.x;
    float M = -INFINITY, S = 0.f;
    for (int b = threadIdx.x; b < NBLK; b += 256)
        comb(M, S, g_pm[(size_t)o * NBLK + b], g_ps[(size_t)o * NBLK + b]);
#pragma unroll
    for (int off = 16; off; off >>= 1) {
        float m2 = __shfl_xor_sync(0xffffffffu, M, off);
        float s2 = __shfl_xor_sync(0xffffffffu, S, off);
        comb(M, S, m2, s2);
    }
    __shared__ float sm[8], ss[8];
    int wq = threadIdx.x >> 5, lane = threadIdx.x & 31;
    if (lane == 0) { sm[wq] = M; ss[wq] = S; }
    __syncthreads();
    if (threadIdx.x == 0) {
#pragma unroll
        for (int i = 1; i < 8; i++) comb(sm[0], ss[0], sm[i], ss[i]);
        g_max[o]  = sm[0];
        g_sinv[o] = 1.0f / ss[0];
    }
}

// ---------------- 6) final: thresholded exp + normalize ----------------------
__global__ void k_final2(float* __restrict__ out) {
    int base = blockIdx.x * 512 + threadIdx.x;
#pragma unroll
    for (int h = 0; h < 2; h++) {
        int f = base + h * 256;
        float4 v = ((const float4*)out)[f];
        int og = f & 31;
        float4 M = ((const float4*)g_max)[og];
        float4 I = ((const float4*)g_sinv)[og];
        float t0 = v.x - M.x, t1 = v.y - M.y, t2 = v.z - M.z, t3 = v.w - M.w;
        v.x = (t0 > -87.f) ? __expf(t0) * I.x : 0.f;
        v.y = (t1 > -87.f) ? __expf(t1) * I.y : 0.f;
        v.z = (t2 > -87.f) ? __expf(t2) * I.z : 0.f;
        v.w = (t3 > -87.f) ? __expf(t3) * I.w : 0.f;
        ((float4*)out)[f] = v;
    }
}

// ---------------- launcher ---------------------------------------------------
extern "C" void kernel_launch(void* const* d_in, const int* in_sizes, int n_in,
                              void* d_out, int out_size) {
    const float* x      = (const float*)d_in[0];
    const float* U      = (const float*)d_in[1];
    const float* coeffs = (const float*)d_in[2];
    float* out = (float*)d_out;

    cudaFuncSetAttribute(k_gemm1_mma, cudaFuncAttributeMaxDynamicSharedMemorySize,
                         G1_SM);
    cudaFuncSetAttribute(k_gemm3_p, cudaFuncAttributeMaxDynamicSharedMemorySize,
                         SM_TOT);

    k_gemm1_mma<<<NBLK, 512, G1_SM>>>(U, x);
    k_rsum<<<64, 256>>>();
    k_mixed_w<<<512, 256>>>(coeffs);
    k_gemm3_p<<<NBLK, 512, SM_TOT>>>(U, out);
    k_softmax_par<<<C, 256>>>();
    k_final2<<<N_TOK * C / 4 / 512, 256>>>(out);
}